// round 1
// baseline (speedup 1.0000x reference)
#include <cuda_runtime.h>
#include <math_constants.h>

// Problem constants
#define NUM_VARS 64
#define KK       32
#define NUM_CATS 256
#define NUM_INPUT (NUM_VARS * KK)   // 2048
#define LL       4
#define EE       16384
#define NN       8192
#define CC       4
#define BB       1024
#define B4       (BB / 4)           // 256 float4 per row
#define TOTAL_NODES (NUM_INPUT + LL * NN)  // 34816
#define NCHUNK   32                 // root reduction chunks

// Scratch: full node-marginal pool (34816 x 1024 fp32 = 142.6 MB) + root partials
__device__ float g_node_mars[(size_t)TOTAL_NODES * BB];
__device__ float g_partial[NCHUNK * BB];

// ---------------------------------------------------------------------------
// Kernel 1: input layer. node_mars[v*K+k, b] = input_logp[v, k, inputs[b, v]]
// One block per variable v; stage inputs[:, v] in smem, then stream k x b.
// ---------------------------------------------------------------------------
__global__ void input_kernel(const int* __restrict__ inputs,
                             const float* __restrict__ input_logp) {
    __shared__ int cats[BB];
    const int v = blockIdx.x;
    for (int b = threadIdx.x; b < BB; b += blockDim.x)
        cats[b] = inputs[b * NUM_VARS + v];
    __syncthreads();

    const float* lp = input_logp + (size_t)v * KK * NUM_CATS;
    float* out = g_node_mars + (size_t)v * KK * BB;
    for (int i = threadIdx.x; i < KK * BB; i += blockDim.x) {
        const int k = i >> 10;       // i / 1024
        const int b = i & (BB - 1);  // i % 1024
        out[i] = __ldg(lp + k * NUM_CATS + cats[b]);
    }
}

// ---------------------------------------------------------------------------
// Kernel 2: one sum layer (product layer fused in — em never materialized).
// Block = one sum node n, 256 threads cover B=1024 as float4 segments.
// new[n,b] = lse_c( logw[n,c] + nm[p0(e)] + nm[p1(e)] ),  e = ch_ids[n,c]
// ---------------------------------------------------------------------------
__device__ __forceinline__ float lse4(float a, float b, float c, float d) {
    float m = fmaxf(fmaxf(a, b), fmaxf(c, d));
    float s = __expf(a - m) + __expf(b - m) + __expf(c - m) + __expf(d - m);
    return m + __logf(s);
}

__global__ void layer_kernel(const int2*  __restrict__ prod,    // E pairs (this layer)
                             const int4*  __restrict__ ch_ids,  // N (this layer)
                             const float4* __restrict__ logw,   // N (this layer)
                             int out_base) {
    const int n  = blockIdx.x;
    const int b4 = threadIdx.x;  // float4 column index, 0..255

    const int4   ch = __ldg(ch_ids + n);
    const float4 w  = __ldg(logw + n);
    const int   es[4] = {ch.x, ch.y, ch.z, ch.w};
    const float ws[4] = {w.x, w.y, w.z, w.w};

    const float4* nm = reinterpret_cast<const float4*>(g_node_mars);

    float4 x[CC];
#pragma unroll
    for (int c = 0; c < CC; c++) {
        const int2 p = __ldg(prod + es[c]);
        const float4 a  = __ldg(nm + (size_t)p.x * B4 + b4);
        const float4 bb = __ldg(nm + (size_t)p.y * B4 + b4);
        x[c].x = a.x + bb.x + ws[c];
        x[c].y = a.y + bb.y + ws[c];
        x[c].z = a.z + bb.z + ws[c];
        x[c].w = a.w + bb.w + ws[c];
    }

    float4 out;
    out.x = lse4(x[0].x, x[1].x, x[2].x, x[3].x);
    out.y = lse4(x[0].y, x[1].y, x[2].y, x[3].y);
    out.z = lse4(x[0].z, x[1].z, x[2].z, x[3].z);
    out.w = lse4(x[0].w, x[1].w, x[2].w, x[3].w);

    reinterpret_cast<float4*>(g_node_mars)[(size_t)(out_base + n) * B4 + b4] = out;
}

// ---------------------------------------------------------------------------
// Kernel 3: root partial logsumexp. grid = (NCHUNK, B/256).
// Each thread: one b, online-lse over a 256-node chunk (coalesced across lanes).
// ---------------------------------------------------------------------------
__global__ void root_partial_kernel(const float* __restrict__ root_logw) {
    const int chunk = blockIdx.x;
    const int b = blockIdx.y * blockDim.x + threadIdx.x;
    const float* last = g_node_mars + (size_t)(NUM_INPUT + (LL - 1) * NN) * BB;
    const int n0 = chunk * (NN / NCHUNK);

    float m = -CUDART_INF_F, s = 0.f;
#pragma unroll 4
    for (int i = 0; i < NN / NCHUNK; i++) {
        const int n = n0 + i;
        const float x = __ldg(root_logw + n) + last[(size_t)n * BB + b];
        if (x > m) { s = s * __expf(m - x) + 1.f; m = x; }
        else       { s += __expf(x - m); }
    }
    g_partial[chunk * BB + b] = m + __logf(s);
}

__global__ void root_final_kernel(float* __restrict__ out) {
    const int b = blockIdx.x * blockDim.x + threadIdx.x;
    float m = -CUDART_INF_F, s = 0.f;
#pragma unroll
    for (int c = 0; c < NCHUNK; c++) {
        const float x = g_partial[c * BB + b];
        if (x > m) { s = s * __expf(m - x) + 1.f; m = x; }
        else       { s += __expf(x - m); }
    }
    out[b] = m + __logf(s);
}

// ---------------------------------------------------------------------------
// Launch: inputs order = inputs, input_logp, prod_ids, sum_ch_ids, sum_logw,
//         root_logw. Output = (B, 1) float.
// ---------------------------------------------------------------------------
extern "C" void kernel_launch(void* const* d_in, const int* in_sizes, int n_in,
                              void* d_out, int out_size) {
    const int*   inputs     = (const int*)  d_in[0];
    const float* input_logp = (const float*)d_in[1];
    const int*   prod_ids   = (const int*)  d_in[2];  // (L, E, 2)
    const int*   sum_ch_ids = (const int*)  d_in[3];  // (L, N, C)
    const float* sum_logw   = (const float*)d_in[4];  // (L, N, C)
    const float* root_logw  = (const float*)d_in[5];  // (N,)
    float* out = (float*)d_out;

    input_kernel<<<NUM_VARS, 256>>>(inputs, input_logp);

    for (int l = 0; l < LL; l++) {
        const int2*   prod = reinterpret_cast<const int2*>(prod_ids + (size_t)l * EE * 2);
        const int4*   chid = reinterpret_cast<const int4*>(sum_ch_ids + (size_t)l * NN * CC);
        const float4* lw   = reinterpret_cast<const float4*>(sum_logw + (size_t)l * NN * CC);
        layer_kernel<<<NN, 256>>>(prod, chid, lw, NUM_INPUT + l * NN);
    }

    dim3 rp_grid(NCHUNK, BB / 256);
    root_partial_kernel<<<rp_grid, 256>>>(root_logw);
    root_final_kernel<<<BB / 256, 256>>>(out);
}

// round 2
// speedup vs baseline: 1.0206x; 1.0206x over previous
#include <cuda_runtime.h>
#include <math_constants.h>

// Problem constants
#define NUM_VARS 64
#define KK       32
#define NUM_CATS 256
#define NUM_INPUT (NUM_VARS * KK)   // 2048
#define LL       4
#define EE       16384
#define NN       8192
#define CC       4
#define BB       1024
#define B4       (BB / 4)           // 256 float4 per row
#define TOTAL_NODES (NUM_INPUT + LL * NN)  // 34816
#define NCHUNK   32                 // root reduction chunks
#define BCHUNKS  2                  // batch tiles for L2 residency
#define B4C      (B4 / BCHUNKS)     // float4 cols per batch tile (128)

// Scratch: node-marginal pool (142.6 MB), root partials, resolved pair indices
__device__ float g_node_mars[(size_t)TOTAL_NODES * BB];
__device__ float g_partial[NCHUNK * BB];
__device__ int2  g_pairs[LL * NN * CC];   // (l,n,c) -> (p0,p1) resolved product pair

// ---------------------------------------------------------------------------
// Kernel 0: resolve the ch_ids -> prod_ids indirection once per call.
// g_pairs[l,n,c] = prod_ids[l, sum_ch_ids[l,n,c]]
// ---------------------------------------------------------------------------
__global__ void resolve_kernel(const int* __restrict__ sum_ch_ids,
                               const int2* __restrict__ prod_ids) {
    const int idx = blockIdx.x * blockDim.x + threadIdx.x;  // over L*N*C
    const int l = idx / (NN * CC);
    const int e = __ldg(sum_ch_ids + idx);
    g_pairs[idx] = __ldg(prod_ids + (size_t)l * EE + e);
}

// ---------------------------------------------------------------------------
// Kernel 1: input layer. node_mars[v*K+k, b] = input_logp[v, k, inputs[b, v]]
// ---------------------------------------------------------------------------
__global__ void input_kernel(const int* __restrict__ inputs,
                             const float* __restrict__ input_logp) {
    __shared__ int cats[BB];
    const int v = blockIdx.x;
    for (int b = threadIdx.x; b < BB; b += blockDim.x)
        cats[b] = inputs[b * NUM_VARS + v];
    __syncthreads();

    const float* lp = input_logp + (size_t)v * KK * NUM_CATS;
    float* out = g_node_mars + (size_t)v * KK * BB;
    for (int i = threadIdx.x; i < KK * BB; i += blockDim.x) {
        const int k = i >> 10;
        const int b = i & (BB - 1);
        out[i] = __ldg(lp + k * NUM_CATS + cats[b]);
    }
}

// ---------------------------------------------------------------------------
// Kernel 2: one sum layer on one batch tile (product layer fused; em never
// materialized; indirection pre-resolved). Block = node n, 128 threads cover
// the tile's 512 columns as float4 segments.
// ---------------------------------------------------------------------------
__device__ __forceinline__ float lse4(float a, float b, float c, float d) {
    float m = fmaxf(fmaxf(a, b), fmaxf(c, d));
    float s = __expf(a - m) + __expf(b - m) + __expf(c - m) + __expf(d - m);
    return m + __logf(s);
}

__global__ void __launch_bounds__(B4C)
layer_kernel(const float4* __restrict__ logw,  // N entries (this layer)
             int l, int out_base, int bc) {
    const int n  = blockIdx.x;
    const int b4 = bc * B4C + threadIdx.x;

    const int4* pr = reinterpret_cast<const int4*>(g_pairs) + ((size_t)l * NN + n) * 2;
    const int4 pa = __ldg(pr);      // {p0_0, p1_0, p0_1, p1_1}
    const int4 pb = __ldg(pr + 1);  // {p0_2, p1_2, p0_3, p1_3}
    const float4 w = __ldg(logw + n);

    const float4* nm = reinterpret_cast<const float4*>(g_node_mars);

    // 8 independent gathers — all issued before any consumption
    const float4 a0 = __ldg(nm + (size_t)pa.x * B4 + b4);
    const float4 c0 = __ldg(nm + (size_t)pa.y * B4 + b4);
    const float4 a1 = __ldg(nm + (size_t)pa.z * B4 + b4);
    const float4 c1 = __ldg(nm + (size_t)pa.w * B4 + b4);
    const float4 a2 = __ldg(nm + (size_t)pb.x * B4 + b4);
    const float4 c2 = __ldg(nm + (size_t)pb.y * B4 + b4);
    const float4 a3 = __ldg(nm + (size_t)pb.z * B4 + b4);
    const float4 c3 = __ldg(nm + (size_t)pb.w * B4 + b4);

    float4 x0, x1, x2, x3;
    x0.x = a0.x + c0.x + w.x; x0.y = a0.y + c0.y + w.x; x0.z = a0.z + c0.z + w.x; x0.w = a0.w + c0.w + w.x;
    x1.x = a1.x + c1.x + w.y; x1.y = a1.y + c1.y + w.y; x1.z = a1.z + c1.z + w.y; x1.w = a1.w + c1.w + w.y;
    x2.x = a2.x + c2.x + w.z; x2.y = a2.y + c2.y + w.z; x2.z = a2.z + c2.z + w.z; x2.w = a2.w + c2.w + w.z;
    x3.x = a3.x + c3.x + w.w; x3.y = a3.y + c3.y + w.w; x3.z = a3.z + c3.z + w.w; x3.w = a3.w + c3.w + w.w;

    float4 out;
    out.x = lse4(x0.x, x1.x, x2.x, x3.x);
    out.y = lse4(x0.y, x1.y, x2.y, x3.y);
    out.z = lse4(x0.z, x1.z, x2.z, x3.z);
    out.w = lse4(x0.w, x1.w, x2.w, x3.w);

    reinterpret_cast<float4*>(g_node_mars)[(size_t)(out_base + n) * B4 + b4] = out;
}

// ---------------------------------------------------------------------------
// Kernel 3: root partial logsumexp + final combine.
// ---------------------------------------------------------------------------
__global__ void root_partial_kernel(const float* __restrict__ root_logw) {
    const int chunk = blockIdx.x;
    const int b = blockIdx.y * blockDim.x + threadIdx.x;
    const float* last = g_node_mars + (size_t)(NUM_INPUT + (LL - 1) * NN) * BB;
    const int n0 = chunk * (NN / NCHUNK);

    float m = -CUDART_INF_F, s = 0.f;
#pragma unroll 4
    for (int i = 0; i < NN / NCHUNK; i++) {
        const int n = n0 + i;
        const float x = __ldg(root_logw + n) + last[(size_t)n * BB + b];
        if (x > m) { s = s * __expf(m - x) + 1.f; m = x; }
        else       { s += __expf(x - m); }
    }
    g_partial[chunk * BB + b] = m + __logf(s);
}

__global__ void root_final_kernel(float* __restrict__ out) {
    const int b = blockIdx.x * blockDim.x + threadIdx.x;
    float m = -CUDART_INF_F, s = 0.f;
#pragma unroll
    for (int c = 0; c < NCHUNK; c++) {
        const float x = g_partial[c * BB + b];
        if (x > m) { s = s * __expf(m - x) + 1.f; m = x; }
        else       { s += __expf(x - m); }
    }
    out[b] = m + __logf(s);
}

// ---------------------------------------------------------------------------
extern "C" void kernel_launch(void* const* d_in, const int* in_sizes, int n_in,
                              void* d_out, int out_size) {
    const int*   inputs     = (const int*)  d_in[0];
    const float* input_logp = (const float*)d_in[1];
    const int*   prod_ids   = (const int*)  d_in[2];  // (L, E, 2)
    const int*   sum_ch_ids = (const int*)  d_in[3];  // (L, N, C)
    const float* sum_logw   = (const float*)d_in[4];  // (L, N, C)
    const float* root_logw  = (const float*)d_in[5];  // (N,)
    float* out = (float*)d_out;

    resolve_kernel<<<(LL * NN * CC) / 256, 256>>>(
        sum_ch_ids, reinterpret_cast<const int2*>(prod_ids));

    input_kernel<<<NUM_VARS, 256>>>(inputs, input_logp);

    // Batch-tiled layer sweep: each tile's 71 MB working set stays L2-resident
    for (int bc = 0; bc < BCHUNKS; bc++) {
        for (int l = 0; l < LL; l++) {
            const float4* lw = reinterpret_cast<const float4*>(sum_logw + (size_t)l * NN * CC);
            layer_kernel<<<NN, B4C>>>(lw, l, NUM_INPUT + l * NN, bc);
        }
    }

    dim3 rp_grid(NCHUNK, BB / 256);
    root_partial_kernel<<<rp_grid, 256>>>(root_logw);
    root_final_kernel<<<BB / 256, 256>>>(out);
}